// round 15
// baseline (speedup 1.0000x reference)
#include <cuda_runtime.h>
#include <cuda_fp16.h>

// Problem constants (fixed by the reference)
#define NN   100000
#define NE   1600000
#define CAP  96            // padded adjacency capacity (Poisson(16): P(deg>=96) ~ 0)
#define FULL 0xFFFFFFFFu
#define MIDT 256           // k_mid block size (nodes per block)
#define MIDB ((NN + MIDT - 1) / MIDT)

// Scratch (device globals — no allocation allowed in kernel_launch).
// INVARIANT: g_cnt is all-zero at entry of every kernel_launch call:
// zero-initialized at module load; k_tail re-zeroes it at the end of each call.
__device__ __align__(16) int     g_cnt  [NN];        // in-degree counters
__device__ __align__(16) int     g_adj  [NN * CAP];  // padded adjacency (src per dst)
__device__ __align__(16) float   g_dinv [NN];
__device__ __align__(16) __half2 g_hs1h [NN * 4];    // dinv-scaled raw feats, fp16 (5 of 8)
__device__ __align__(16) __half2 g_hs2h [NN * 16];   // dinv-scaled layer-2 messages (fp16)

// Packed dual-fp32 FMA (Blackwell fma.rn.f32x2): acc += a * b elementwise.
__device__ __forceinline__ void ffma2(unsigned long long& acc,
                                      unsigned long long a,
                                      unsigned long long b) {
    asm("fma.rn.f32x2 %0, %1, %2, %0;" : "+l"(acc) : "l"(a), "l"(b));
}

// ---------------------------------------------------------------------------
// Adjacency build straight from edge_index. Per-block dtype detection:
// int64 buffers have all-zero odd 32-bit words (nonneg indices < 2^31).
// ---------------------------------------------------------------------------
__global__ void k_place(const void* __restrict__ ei) {
    __shared__ int s_is64;
    if (threadIdx.x == 0) {
        const int* w = (const int*)ei;
        int all_zero = 1;
        for (int k = 0; k < 48; k++)
            if (w[2 * k + 1] != 0) { all_zero = 0; break; }
        s_is64 = all_zero;
    }
    __syncthreads();

    int e = blockIdx.x * blockDim.x + threadIdx.x;
    if (e >= NE) return;
    int src, dst;
    if (s_is64) {
        src = (int)((const long long*)ei)[e];
        dst = (int)((const long long*)ei)[(long long)NE + e];
    } else {
        src = ((const int*)ei)[e];
        dst = ((const int*)ei)[NE + e];
    }
    int pos = atomicAdd(&g_cnt[dst], 1);
    if (pos < CAP) g_adj[dst * CAP + pos] = src;
}

// ---------------------------------------------------------------------------
// dinv = rsqrt(deg+1); hs1 = fp16(edge_attr * dinv), 16B row per node.
// ---------------------------------------------------------------------------
__global__ void k_dinv_prescale(const float* __restrict__ x) {
    int i = blockIdx.x * blockDim.x + threadIdx.x;
    if (i >= NN) return;
    float d = rsqrtf((float)(g_cnt[i] + 1));
    g_dinv[i] = d;
    __half2 h[4];
    h[0] = __floats2half2_rn(x[i * 5 + 0] * d, x[i * 5 + 1] * d);
    h[1] = __floats2half2_rn(x[i * 5 + 2] * d, x[i * 5 + 3] * d);
    h[2] = __floats2half2_rn(x[i * 5 + 4] * d, 0.f);
    h[3] = __floats2half2_rn(0.f, 0.f);
    *(uint4*)&g_hs1h[i * 4] = *(const uint4*)h;
}

// ---------------------------------------------------------------------------
// Fused middle, block = 256 nodes (R14 winning config, unchanged):
//  Phase A (4 lanes/node): Σ hs1h[src] (+ self) -> SMEM; ONE LDG.128 per edge.
//  Phase B (thread=node): agg*dinv -> x1=relu(·W1+b1) on the fly ->
//    hs2 = (x1@W2)*dinv, packed f32x2 accumulators, stored as fp16 (half2).
// ---------------------------------------------------------------------------
__global__ void __launch_bounds__(MIDT) k_mid(const float* __restrict__ W1,
                                              const float* __restrict__ b1,
                                              const float* __restrict__ W2) {
    __shared__ float sW1[5 * 64];
    __shared__ float sb1[64];
    __shared__ __align__(16) float sW2[64 * 32];
    __shared__ float sAgg[MIDT * 5];

    int tid = threadIdx.x;
    for (int k = tid; k < 5 * 64; k += MIDT) sW1[k] = W1[k];
    if (tid < 64) sb1[tid] = b1[tid];
    for (int k = tid; k < 64 * 32; k += MIDT) sW2[k] = W2[k];
    __syncthreads();

    int wl    = tid >> 5;
    int lane  = tid & 31;
    int group = lane >> 2;     // 8 node-groups per warp
    int sub   = lane & 3;      // 4 lanes per node

    // ---- Phase A: aggregation (self loop folded in as edge index == deg) ----
#pragma unroll
    for (int it = 0; it < MIDT / 64; it++) {
        int local = it * 64 + wl * 8 + group;
        int node  = blockIdx.x * MIDT + local;
        float a0 = 0.f, a1 = 0.f, a2 = 0.f, a3 = 0.f, a4 = 0.f;
        if (node < NN) {
            int deg = min(g_cnt[node], CAP);
            const int* row = &g_adj[node * CAP];
            for (int e = sub; e <= deg; e += 4) {   // e == deg -> self loop
                int s = (e < deg) ? row[e] : node;
                uint4 raw = *(const uint4*)&g_hs1h[s * 4];   // one 16B load
                const __half2* hp = (const __half2*)&raw;
                float2 f0 = __half22float2(hp[0]);
                float2 f1 = __half22float2(hp[1]);
                float2 f2 = __half22float2(hp[2]);
                a0 += f0.x; a1 += f0.y; a2 += f1.x; a3 += f1.y; a4 += f2.x;
            }
        }
        a0 += __shfl_xor_sync(FULL, a0, 1);  a0 += __shfl_xor_sync(FULL, a0, 2);
        a1 += __shfl_xor_sync(FULL, a1, 1);  a1 += __shfl_xor_sync(FULL, a1, 2);
        a2 += __shfl_xor_sync(FULL, a2, 1);  a2 += __shfl_xor_sync(FULL, a2, 2);
        a3 += __shfl_xor_sync(FULL, a3, 1);  a3 += __shfl_xor_sync(FULL, a3, 2);
        a4 += __shfl_xor_sync(FULL, a4, 1);  a4 += __shfl_xor_sync(FULL, a4, 2);
        if (sub == 0 && node < NN) {
            sAgg[local * 5 + 0] = a0;
            sAgg[local * 5 + 1] = a1;
            sAgg[local * 5 + 2] = a2;
            sAgg[local * 5 + 3] = a3;
            sAgg[local * 5 + 4] = a4;
        }
    }
    __syncthreads();

    // ---- Phase B: transform, one node per thread ----
    int node = blockIdx.x * MIDT + tid;
    if (node >= NN) return;
    float d  = g_dinv[node];                 // coalesced
    float a0 = sAgg[tid * 5 + 0] * d;        // stride-5: conflict-free
    float a1 = sAgg[tid * 5 + 1] * d;
    float a2 = sAgg[tid * 5 + 2] * d;
    float a3 = sAgg[tid * 5 + 3] * d;
    float a4 = sAgg[tid * 5 + 4] * d;

    unsigned long long acc2[16];
#pragma unroll
    for (int j = 0; j < 16; j++) acc2[j] = 0ull;

#pragma unroll 4
    for (int k = 0; k < 64; k++) {
        float x1k = sb1[k];
        x1k = fmaf(a0, sW1[0 * 64 + k], x1k);
        x1k = fmaf(a1, sW1[1 * 64 + k], x1k);
        x1k = fmaf(a2, sW1[2 * 64 + k], x1k);
        x1k = fmaf(a3, sW1[3 * 64 + k], x1k);
        x1k = fmaf(a4, sW1[4 * 64 + k], x1k);
        x1k = fmaxf(x1k, 0.f);
        unsigned long long xk2;
        asm("mov.b64 %0, {%1, %1};" : "=l"(xk2) : "r"(__float_as_uint(x1k)));
#pragma unroll
        for (int j4 = 0; j4 < 8; j4++) {
            ulonglong2 w2 = *(const ulonglong2*)&sW2[k * 32 + j4 * 4]; // broadcast
            ffma2(acc2[j4 * 2 + 0], xk2, w2.x);
            ffma2(acc2[j4 * 2 + 1], xk2, w2.y);
        }
    }

    // Store hs2 as fp16 (half2 pairs), 4 x 16B stores per node.
#pragma unroll
    for (int q = 0; q < 4; q++) {
        __half2 hh[4];
#pragma unroll
        for (int t = 0; t < 4; t++) {
            unsigned lo, hi;
            asm("mov.b64 {%0, %1}, %2;" : "=r"(lo), "=r"(hi) : "l"(acc2[q * 4 + t]));
            hh[t] = __floats2half2_rn(__uint_as_float(lo) * d,
                                      __uint_as_float(hi) * d);
        }
        *(uint4*)&g_hs2h[node * 16 + q * 4] = *(const uint4*)hh;
    }
}

// ---------------------------------------------------------------------------
// Fused tail (one warp per node) + g_cnt re-zero for the next call:
//   lane = half_id*16 + h; h = feature-pair, half_id picks odd/even edges.
//   acc(float2) = hs2h[n] + Σ hs2h[src]   [2 edges per warp instruction]
//   combine halves (shfl_xor 16); x2 = relu(acc*dinv + b2);
//   x3 = relu(x2@fcW1 + fcb1); out = x3@fcW2 + fcb2
// ---------------------------------------------------------------------------
__global__ void __launch_bounds__(256) k_tail(const float* __restrict__ b2,
                                              const float* __restrict__ fcW1,
                                              const float* __restrict__ fcb1,
                                              const float* __restrict__ fcW2,
                                              const float* __restrict__ fcb2,
                                              float* __restrict__ out) {
    __shared__ float sb2[32];
    __shared__ float sfcW1[32 * 16];
    __shared__ float sfcb1[16];
    __shared__ float sfcW2[32];
    __shared__ float sfcb2[2];
    __shared__ float sx2[8][32];
    __shared__ float sx3[8][16];

    int tid = threadIdx.x;
    if (tid < 32) sb2[tid] = b2[tid];
    for (int k = tid; k < 32 * 16; k += 256) sfcW1[k] = fcW1[k];
    if (tid < 16) sfcb1[tid] = fcb1[tid];
    if (tid >= 32 && tid < 64) sfcW2[tid - 32] = fcW2[tid - 32];
    if (tid >= 64 && tid < 66) sfcb2[tid - 64] = fcb2[tid - 64];
    __syncthreads();

    int wl   = tid >> 5;
    int lane = tid & 31;
    int h    = lane & 15;    // feature pair (2h, 2h+1)
    int hid  = lane >> 4;    // 0: even edges + self, 1: odd edges
    int node = blockIdx.x * 8 + wl;

    int deg = min(g_cnt[node], CAP);
    if (lane == 0) g_cnt[node] = 0;   // restore invariant for next call
    const int* row = &g_adj[node * CAP];

    float2 acc0 = make_float2(0.f, 0.f), acc1 = acc0, acc2 = acc0, acc3 = acc0;
    if (hid == 0)                          // self loop on half 0 only
        acc0 = __half22float2(g_hs2h[node * 16 + h]);

    int e = 0;
    for (; e + 8 <= deg; e += 8) {
        int s0 = row[e + 0 + hid], s1 = row[e + 2 + hid];
        int s2 = row[e + 4 + hid], s3 = row[e + 6 + hid];
        float2 v0 = __half22float2(g_hs2h[s0 * 16 + h]);
        float2 v1 = __half22float2(g_hs2h[s1 * 16 + h]);
        float2 v2 = __half22float2(g_hs2h[s2 * 16 + h]);
        float2 v3 = __half22float2(g_hs2h[s3 * 16 + h]);
        acc0.x += v0.x; acc0.y += v0.y;
        acc1.x += v1.x; acc1.y += v1.y;
        acc2.x += v2.x; acc2.y += v2.y;
        acc3.x += v3.x; acc3.y += v3.y;
    }
    for (int r = e + hid; r < deg; r += 2) {
        float2 v = __half22float2(g_hs2h[row[r] * 16 + h]);
        acc0.x += v.x; acc0.y += v.y;
    }

    float ax = (acc0.x + acc1.x) + (acc2.x + acc3.x);
    float ay = (acc0.y + acc1.y) + (acc2.y + acc3.y);
    ax += __shfl_xor_sync(FULL, ax, 16);   // combine halves
    ay += __shfl_xor_sync(FULL, ay, 16);

    float d = g_dinv[node];
    if (lane < 16) {
        sx2[wl][2 * h + 0] = fmaxf(fmaf(ax, d, sb2[2 * h + 0]), 0.f);
        sx2[wl][2 * h + 1] = fmaxf(fmaf(ay, d, sb2[2 * h + 1]), 0.f);
    }
    __syncwarp();

    if (lane < 16) {
        float x3 = sfcb1[lane];
#pragma unroll
        for (int j = 0; j < 32; j++)
            x3 = fmaf(sx2[wl][j], sfcW1[j * 16 + lane], x3);
        sx3[wl][lane] = fmaxf(x3, 0.f);
    }
    __syncwarp();

    if (lane < 2) {
        float o = sfcb2[lane];
#pragma unroll
        for (int m = 0; m < 16; m++)
            o = fmaf(sx3[wl][m], sfcW2[m * 2 + lane], o);
        out[node * 2 + lane] = o;
    }
}

// ---------------------------------------------------------------------------
// Launch — 4 kernels total (k_init eliminated; g_cnt zeroed by k_tail)
// ---------------------------------------------------------------------------
extern "C" void kernel_launch(void* const* d_in, const int* in_sizes, int n_in,
                              void* d_out, int out_size) {
    const float* edge_attr = (const float*)d_in[0];
    const void*  edge_idx  = d_in[1];
    const float* W1   = (const float*)d_in[2];
    const float* b1   = (const float*)d_in[3];
    const float* W2   = (const float*)d_in[4];
    const float* b2   = (const float*)d_in[5];
    const float* fcW1 = (const float*)d_in[6];
    const float* fcb1 = (const float*)d_in[7];
    const float* fcW2 = (const float*)d_in[8];
    const float* fcb2 = (const float*)d_in[9];
    float* out = (float*)d_out;

    const int T = 256;

    k_place<<<(NE + T - 1) / T, T>>>(edge_idx);
    k_dinv_prescale<<<(NN + T - 1) / T, T>>>(edge_attr);
    k_mid  <<<MIDB, MIDT>>>(W1, b1, W2);
    k_tail <<<NN / 8, 256>>>(b2, fcW1, fcb1, fcW2, fcb2, out);
}

// round 16
// speedup vs baseline: 1.4797x; 1.4797x over previous
#include <cuda_runtime.h>
#include <cuda_fp16.h>

// Problem constants (fixed by the reference)
#define NN   100000
#define NE   1600000
#define CAP  96            // padded adjacency capacity (Poisson(16): P(deg>=96) ~ 0)
#define FULL 0xFFFFFFFFu
#define MIDT 256           // k_mid block size (nodes per block)
#define MIDB ((NN + MIDT - 1) / MIDT)

// Scratch (device globals — no allocation allowed in kernel_launch)
__device__ int g_is64;
__device__ __align__(16) int     g_cnt  [NN];        // in-degree counters
__device__ __align__(16) int     g_adj  [NN * CAP];  // padded adjacency (src per dst)
__device__ __align__(16) float   g_dinv [NN];
__device__ __align__(16) __half2 g_hs1h [NN * 4];    // dinv-scaled raw feats, fp16 (5 of 8)
__device__ __align__(16) __half2 g_hs2h [NN * 16];   // dinv-scaled layer-2 messages (fp16)

// Packed dual-fp32 FMA (Blackwell fma.rn.f32x2): acc += a * b elementwise.
__device__ __forceinline__ void ffma2(unsigned long long& acc,
                                      unsigned long long a,
                                      unsigned long long b) {
    asm("fma.rn.f32x2 %0, %1, %2, %0;" : "+l"(acc) : "l"(a), "l"(b));
}

// ---------------------------------------------------------------------------
// Fused: zero counters + dtype detect (int64 => odd 32-bit words all zero).
// ---------------------------------------------------------------------------
__global__ void k_init(const int* __restrict__ ei32) {
    int i = blockIdx.x * blockDim.x + threadIdx.x;
    if (i < NN) g_cnt[i] = 0;
    if (i == 0) {
        int all_zero = 1;
        for (int k = 0; k < 48; k++)
            if (ei32[2 * k + 1] != 0) { all_zero = 0; break; }
        g_is64 = all_zero;
    }
}

// ---------------------------------------------------------------------------
// Single-pass adjacency build straight from edge_index.
// ---------------------------------------------------------------------------
__global__ void k_place(const void* __restrict__ ei) {
    int e = blockIdx.x * blockDim.x + threadIdx.x;
    if (e >= NE) return;
    int src, dst;
    if (g_is64) {
        src = (int)((const long long*)ei)[e];
        dst = (int)((const long long*)ei)[(long long)NE + e];
    } else {
        src = ((const int*)ei)[e];
        dst = ((const int*)ei)[NE + e];
    }
    int pos = atomicAdd(&g_cnt[dst], 1);
    if (pos < CAP) g_adj[dst * CAP + pos] = src;
}

// ---------------------------------------------------------------------------
// dinv = rsqrt(deg+1); hs1 = fp16(edge_attr * dinv), 16B row per node.
// ---------------------------------------------------------------------------
__global__ void k_dinv_prescale(const float* __restrict__ x) {
    int i = blockIdx.x * blockDim.x + threadIdx.x;
    if (i >= NN) return;
    float d = rsqrtf((float)(g_cnt[i] + 1));
    g_dinv[i] = d;
    __half2 h[4];
    h[0] = __floats2half2_rn(x[i * 5 + 0] * d, x[i * 5 + 1] * d);
    h[1] = __floats2half2_rn(x[i * 5 + 2] * d, x[i * 5 + 3] * d);
    h[2] = __floats2half2_rn(x[i * 5 + 4] * d, 0.f);
    h[3] = __floats2half2_rn(0.f, 0.f);
    *(uint4*)&g_hs1h[i * 4] = *(const uint4*)h;
}

// ---------------------------------------------------------------------------
// Fused middle, block = 256 nodes (R14 winning config, unchanged):
//  Phase A (4 lanes/node): Σ hs1h[src] (+ self) -> SMEM; ONE LDG.128 per edge.
//  Phase B (thread=node): agg*dinv -> x1=relu(·W1+b1) on the fly ->
//    hs2 = (x1@W2)*dinv, packed f32x2 accumulators, stored as fp16 (half2).
// ---------------------------------------------------------------------------
__global__ void __launch_bounds__(MIDT) k_mid(const float* __restrict__ W1,
                                              const float* __restrict__ b1,
                                              const float* __restrict__ W2) {
    __shared__ float sW1[5 * 64];
    __shared__ float sb1[64];
    __shared__ __align__(16) float sW2[64 * 32];
    __shared__ float sAgg[MIDT * 5];

    int tid = threadIdx.x;
    for (int k = tid; k < 5 * 64; k += MIDT) sW1[k] = W1[k];
    if (tid < 64) sb1[tid] = b1[tid];
    for (int k = tid; k < 64 * 32; k += MIDT) sW2[k] = W2[k];
    __syncthreads();

    int wl    = tid >> 5;
    int lane  = tid & 31;
    int group = lane >> 2;     // 8 node-groups per warp
    int sub   = lane & 3;      // 4 lanes per node

    // ---- Phase A: aggregation (self loop folded in as edge index == deg) ----
#pragma unroll
    for (int it = 0; it < MIDT / 64; it++) {
        int local = it * 64 + wl * 8 + group;
        int node  = blockIdx.x * MIDT + local;
        float a0 = 0.f, a1 = 0.f, a2 = 0.f, a3 = 0.f, a4 = 0.f;
        if (node < NN) {
            int deg = min(g_cnt[node], CAP);
            const int* row = &g_adj[node * CAP];
            for (int e = sub; e <= deg; e += 4) {   // e == deg -> self loop
                int s = (e < deg) ? row[e] : node;
                uint4 raw = *(const uint4*)&g_hs1h[s * 4];   // one 16B load
                const __half2* hp = (const __half2*)&raw;
                float2 f0 = __half22float2(hp[0]);
                float2 f1 = __half22float2(hp[1]);
                float2 f2 = __half22float2(hp[2]);
                a0 += f0.x; a1 += f0.y; a2 += f1.x; a3 += f1.y; a4 += f2.x;
            }
        }
        a0 += __shfl_xor_sync(FULL, a0, 1);  a0 += __shfl_xor_sync(FULL, a0, 2);
        a1 += __shfl_xor_sync(FULL, a1, 1);  a1 += __shfl_xor_sync(FULL, a1, 2);
        a2 += __shfl_xor_sync(FULL, a2, 1);  a2 += __shfl_xor_sync(FULL, a2, 2);
        a3 += __shfl_xor_sync(FULL, a3, 1);  a3 += __shfl_xor_sync(FULL, a3, 2);
        a4 += __shfl_xor_sync(FULL, a4, 1);  a4 += __shfl_xor_sync(FULL, a4, 2);
        if (sub == 0 && node < NN) {
            sAgg[local * 5 + 0] = a0;
            sAgg[local * 5 + 1] = a1;
            sAgg[local * 5 + 2] = a2;
            sAgg[local * 5 + 3] = a3;
            sAgg[local * 5 + 4] = a4;
        }
    }
    __syncthreads();

    // ---- Phase B: transform, one node per thread ----
    int node = blockIdx.x * MIDT + tid;
    if (node >= NN) return;
    float d  = g_dinv[node];                 // coalesced
    float a0 = sAgg[tid * 5 + 0] * d;        // stride-5: conflict-free
    float a1 = sAgg[tid * 5 + 1] * d;
    float a2 = sAgg[tid * 5 + 2] * d;
    float a3 = sAgg[tid * 5 + 3] * d;
    float a4 = sAgg[tid * 5 + 4] * d;

    unsigned long long acc2[16];
#pragma unroll
    for (int j = 0; j < 16; j++) acc2[j] = 0ull;

#pragma unroll 4
    for (int k = 0; k < 64; k++) {
        float x1k = sb1[k];
        x1k = fmaf(a0, sW1[0 * 64 + k], x1k);
        x1k = fmaf(a1, sW1[1 * 64 + k], x1k);
        x1k = fmaf(a2, sW1[2 * 64 + k], x1k);
        x1k = fmaf(a3, sW1[3 * 64 + k], x1k);
        x1k = fmaf(a4, sW1[4 * 64 + k], x1k);
        x1k = fmaxf(x1k, 0.f);
        unsigned long long xk2;
        asm("mov.b64 %0, {%1, %1};" : "=l"(xk2) : "r"(__float_as_uint(x1k)));
#pragma unroll
        for (int j4 = 0; j4 < 8; j4++) {
            ulonglong2 w2 = *(const ulonglong2*)&sW2[k * 32 + j4 * 4]; // broadcast
            ffma2(acc2[j4 * 2 + 0], xk2, w2.x);
            ffma2(acc2[j4 * 2 + 1], xk2, w2.y);
        }
    }

    // Store hs2 as fp16 (half2 pairs), 4 x 16B stores per node.
#pragma unroll
    for (int q = 0; q < 4; q++) {
        __half2 hh[4];
#pragma unroll
        for (int t = 0; t < 4; t++) {
            unsigned lo, hi;
            asm("mov.b64 {%0, %1}, %2;" : "=r"(lo), "=r"(hi) : "l"(acc2[q * 4 + t]));
            hh[t] = __floats2half2_rn(__uint_as_float(lo) * d,
                                      __uint_as_float(hi) * d);
        }
        *(uint4*)&g_hs2h[node * 16 + q * 4] = *(const uint4*)hh;
    }
}

// ---------------------------------------------------------------------------
// Fused tail (one warp per node):
//   lane = half_id*16 + h; h = feature-pair, half_id picks odd/even edges.
//   16-edge batched stage (8 gathers in flight) then 8-edge stage + remainder.
//   combine halves (shfl_xor 16); x2 = relu(acc*dinv + b2);
//   x3 = relu(x2@fcW1 + fcb1); out = x3@fcW2 + fcb2
// ---------------------------------------------------------------------------
__global__ void __launch_bounds__(256) k_tail(const float* __restrict__ b2,
                                              const float* __restrict__ fcW1,
                                              const float* __restrict__ fcb1,
                                              const float* __restrict__ fcW2,
                                              const float* __restrict__ fcb2,
                                              float* __restrict__ out) {
    __shared__ float sb2[32];
    __shared__ float sfcW1[32 * 16];
    __shared__ float sfcb1[16];
    __shared__ float sfcW2[32];
    __shared__ float sfcb2[2];
    __shared__ float sx2[8][32];
    __shared__ float sx3[8][16];

    int tid = threadIdx.x;
    if (tid < 32) sb2[tid] = b2[tid];
    for (int k = tid; k < 32 * 16; k += 256) sfcW1[k] = fcW1[k];
    if (tid < 16) sfcb1[tid] = fcb1[tid];
    if (tid >= 32 && tid < 64) sfcW2[tid - 32] = fcW2[tid - 32];
    if (tid >= 64 && tid < 66) sfcb2[tid - 64] = fcb2[tid - 64];
    __syncthreads();

    int wl   = tid >> 5;
    int lane = tid & 31;
    int h    = lane & 15;    // feature pair (2h, 2h+1)
    int hid  = lane >> 4;    // 0: even edges + self, 1: odd edges
    int node = blockIdx.x * 8 + wl;

    int deg = min(g_cnt[node], CAP);
    const int* row = &g_adj[node * CAP];

    float2 acc0 = make_float2(0.f, 0.f), acc1 = acc0, acc2 = acc0, acc3 = acc0;
    if (hid == 0)                          // self loop on half 0 only
        acc0 = __half22float2(g_hs2h[node * 16 + h]);

    int e = 0;
    // 16-edge batch: 8 independent gathers in flight
    for (; e + 16 <= deg; e += 16) {
        int s0 = row[e + 0 + hid],  s1 = row[e + 2 + hid];
        int s2 = row[e + 4 + hid],  s3 = row[e + 6 + hid];
        int s4 = row[e + 8 + hid],  s5 = row[e + 10 + hid];
        int s6 = row[e + 12 + hid], s7 = row[e + 14 + hid];
        float2 v0 = __half22float2(g_hs2h[s0 * 16 + h]);
        float2 v1 = __half22float2(g_hs2h[s1 * 16 + h]);
        float2 v2 = __half22float2(g_hs2h[s2 * 16 + h]);
        float2 v3 = __half22float2(g_hs2h[s3 * 16 + h]);
        float2 v4 = __half22float2(g_hs2h[s4 * 16 + h]);
        float2 v5 = __half22float2(g_hs2h[s5 * 16 + h]);
        float2 v6 = __half22float2(g_hs2h[s6 * 16 + h]);
        float2 v7 = __half22float2(g_hs2h[s7 * 16 + h]);
        acc0.x += v0.x; acc0.y += v0.y;
        acc1.x += v1.x; acc1.y += v1.y;
        acc2.x += v2.x; acc2.y += v2.y;
        acc3.x += v3.x; acc3.y += v3.y;
        acc0.x += v4.x; acc0.y += v4.y;
        acc1.x += v5.x; acc1.y += v5.y;
        acc2.x += v6.x; acc2.y += v6.y;
        acc3.x += v7.x; acc3.y += v7.y;
    }
    // 8-edge batch
    for (; e + 8 <= deg; e += 8) {
        int s0 = row[e + 0 + hid], s1 = row[e + 2 + hid];
        int s2 = row[e + 4 + hid], s3 = row[e + 6 + hid];
        float2 v0 = __half22float2(g_hs2h[s0 * 16 + h]);
        float2 v1 = __half22float2(g_hs2h[s1 * 16 + h]);
        float2 v2 = __half22float2(g_hs2h[s2 * 16 + h]);
        float2 v3 = __half22float2(g_hs2h[s3 * 16 + h]);
        acc0.x += v0.x; acc0.y += v0.y;
        acc1.x += v1.x; acc1.y += v1.y;
        acc2.x += v2.x; acc2.y += v2.y;
        acc3.x += v3.x; acc3.y += v3.y;
    }
    for (int r = e + hid; r < deg; r += 2) {
        float2 v = __half22float2(g_hs2h[row[r] * 16 + h]);
        acc0.x += v.x; acc0.y += v.y;
    }

    float ax = (acc0.x + acc1.x) + (acc2.x + acc3.x);
    float ay = (acc0.y + acc1.y) + (acc2.y + acc3.y);
    ax += __shfl_xor_sync(FULL, ax, 16);   // combine halves
    ay += __shfl_xor_sync(FULL, ay, 16);

    float d = g_dinv[node];
    if (lane < 16) {
        sx2[wl][2 * h + 0] = fmaxf(fmaf(ax, d, sb2[2 * h + 0]), 0.f);
        sx2[wl][2 * h + 1] = fmaxf(fmaf(ay, d, sb2[2 * h + 1]), 0.f);
    }
    __syncwarp();

    if (lane < 16) {
        float x3 = sfcb1[lane];
#pragma unroll
        for (int j = 0; j < 32; j++)
            x3 = fmaf(sx2[wl][j], sfcW1[j * 16 + lane], x3);
        sx3[wl][lane] = fmaxf(x3, 0.f);
    }
    __syncwarp();

    if (lane < 2) {
        float o = sfcb2[lane];
#pragma unroll
        for (int m = 0; m < 16; m++)
            o = fmaf(sx3[wl][m], sfcW2[m * 2 + lane], o);
        out[node * 2 + lane] = o;
    }
}

// ---------------------------------------------------------------------------
// Launch — 5 kernels total (R14 structure restored)
// ---------------------------------------------------------------------------
extern "C" void kernel_launch(void* const* d_in, const int* in_sizes, int n_in,
                              void* d_out, int out_size) {
    const float* edge_attr = (const float*)d_in[0];
    const void*  edge_idx  = d_in[1];
    const float* W1   = (const float*)d_in[2];
    const float* b1   = (const float*)d_in[3];
    const float* W2   = (const float*)d_in[4];
    const float* b2   = (const float*)d_in[5];
    const float* fcW1 = (const float*)d_in[6];
    const float* fcb1 = (const float*)d_in[7];
    const float* fcW2 = (const float*)d_in[8];
    const float* fcb2 = (const float*)d_in[9];
    float* out = (float*)d_out;

    const int T = 256;

    k_init <<<(NN + T - 1) / T, T>>>((const int*)edge_idx);
    k_place<<<(NE + T - 1) / T, T>>>(edge_idx);
    k_dinv_prescale<<<(NN + T - 1) / T, T>>>(edge_attr);
    k_mid  <<<MIDB, MIDT>>>(W1, b1, W2);
    k_tail <<<NN / 8, 256>>>(b2, fcW1, fcb1, fcW2, fcb2, out);
}